// round 3
// baseline (speedup 1.0000x reference)
#include <cuda_runtime.h>

#define PP 6
#define NF 10
#define TABLE 7776            // 6^5
#define TABLE4 1944           // 6^5 / 4
#define K4_TOTAL 15116544     // 6^10 / 4

__device__ float g_A[TABLE];
__device__ float g_C[TABLE];
__device__ float g_den;
__device__ float g_num;

__global__ void prep_kernel(const float* __restrict__ X,
                            const float* __restrict__ a,
                            const float* __restrict__ b) {
    __shared__ float h[NF][PP];
    __shared__ float rs[NF];
    int tid = threadIdx.x;
    if (tid < NF * PP) {
        int i = tid / PP;
        float d = a[tid] - X[i];
        float bb = b[tid];
        h[i][tid % PP] = expf(-(d * d) / (2.0f * bb * bb));
    }
    if (tid == 0) g_num = 0.0f;
    __syncthreads();
    if (tid < NF) {
        float s = 0.0f;
        #pragma unroll
        for (int j = 0; j < PP; j++) s += h[tid][j];
        rs[tid] = s;
    }
    __syncthreads();
    if (tid == 0) {
        float d = 1.0f;
        #pragma unroll
        for (int i = 0; i < NF; i++) d *= rs[i];
        g_den = d;
    }
    // Partial-product tables: A over features 0..4, C over features 5..9.
    for (int idx = tid; idx < TABLE; idx += blockDim.x) {
        int t = idx;
        int d4 = t % PP; t /= PP;
        int d3 = t % PP; t /= PP;
        int d2 = t % PP; t /= PP;
        int d1 = t % PP; t /= PP;
        int d0 = t;
        g_A[idx] = h[0][d0] * h[1][d1] * h[2][d2] * h[3][d3] * h[4][d4];
        g_C[idx] = h[5][d0] * h[6][d1] * h[7][d2] * h[8][d3] * h[9][d4];
    }
}

__global__ void __launch_bounds__(256) sum_kernel(const float4* __restrict__ y4) {
    extern __shared__ float smem[];
    float*  sA  = smem;                       // 7776 floats
    float4* sC4 = (float4*)(smem + TABLE);    // 7776 floats as 1944 float4 (16B aligned)

    for (int i = threadIdx.x; i < TABLE; i += blockDim.x) sA[i] = g_A[i];
    const float4* gC4 = (const float4*)g_C;
    for (int i = threadIdx.x; i < TABLE4; i += blockDim.x) sC4[i] = gC4[i];
    __syncthreads();

    float acc = 0.0f;
    int stride = gridDim.x * blockDim.x;
    #pragma unroll 4
    for (int i = blockIdx.x * blockDim.x + threadIdx.x; i < K4_TOTAL; i += stride) {
        float4 yv = __ldg(&y4[i]);
        int hi  = i / TABLE4;                 // same for 1944 consecutive float4s
        int lo4 = i - hi * TABLE4;
        float4 cv = sC4[lo4];                 // LDS.128, consecutive lanes -> conflict-free
        float  w  = sA[hi];                   // warp-uniform broadcast
        acc += w * (yv.x * cv.x + yv.y * cv.y + yv.z * cv.z + yv.w * cv.w);
    }

    // warp reduce
    #pragma unroll
    for (int off = 16; off; off >>= 1)
        acc += __shfl_xor_sync(0xffffffffu, acc, off);

    __shared__ float warp_sums[8];
    int wid = threadIdx.x >> 5;
    int lid = threadIdx.x & 31;
    if (lid == 0) warp_sums[wid] = acc;
    __syncthreads();
    if (wid == 0) {
        float v = (lid < 8) ? warp_sums[lid] : 0.0f;
        #pragma unroll
        for (int off = 4; off; off >>= 1)
            v += __shfl_xor_sync(0xffffffffu, v, off);
        if (lid == 0) atomicAdd(&g_num, v);
    }
}

__global__ void finish_kernel(float* __restrict__ out) {
    out[0] = g_num / g_den;
}

extern "C" void kernel_launch(void* const* d_in, const int* in_sizes, int n_in,
                              void* d_out, int out_size) {
    const float* X = (const float*)d_in[0];
    const float* a = (const float*)d_in[1];
    const float* b = (const float*)d_in[2];
    const float* y = (const float*)d_in[3];
    float* out = (float*)d_out;

    int smem_bytes = 2 * TABLE * (int)sizeof(float);  // 62208 B
    cudaFuncSetAttribute(sum_kernel,
                         cudaFuncAttributeMaxDynamicSharedMemorySize, smem_bytes);

    prep_kernel<<<1, 256>>>(X, a, b);
    sum_kernel<<<444, 256, smem_bytes>>>((const float4*)y);
    finish_kernel<<<1, 1>>>(out);
}

// round 4
// speedup vs baseline: 1.0019x; 1.0019x over previous
#include <cuda_runtime.h>

#define PP 6
#define NF 10
#define TABLE 7776            // 6^5
#define TABLE4 1944           // 6^5 / 4
#define K4_TOTAL 15116544     // 6^10 / 4

__device__ float g_A[TABLE];
__device__ float g_C[TABLE];
__device__ float g_den;
__device__ float g_num;

__global__ void prep_kernel(const float* __restrict__ X,
                            const float* __restrict__ a,
                            const float* __restrict__ b) {
    __shared__ float h[NF][PP];
    __shared__ float rs[NF];
    int tid = threadIdx.x;
    if (tid < NF * PP) {
        int i = tid / PP;
        float d = a[tid] - X[i];
        float bb = b[tid];
        h[i][tid % PP] = expf(-(d * d) / (2.0f * bb * bb));
    }
    if (tid == 0) g_num = 0.0f;
    __syncthreads();
    if (tid < NF) {
        float s = 0.0f;
        #pragma unroll
        for (int j = 0; j < PP; j++) s += h[tid][j];
        rs[tid] = s;
    }
    __syncthreads();
    if (tid == 0) {
        float d = 1.0f;
        #pragma unroll
        for (int i = 0; i < NF; i++) d *= rs[i];
        g_den = d;
    }
    // Partial-product tables: A over features 0..4, C over features 5..9.
    for (int idx = tid; idx < TABLE; idx += blockDim.x) {
        int t = idx;
        int d4 = t % PP; t /= PP;
        int d3 = t % PP; t /= PP;
        int d2 = t % PP; t /= PP;
        int d1 = t % PP; t /= PP;
        int d0 = t;
        g_A[idx] = h[0][d0] * h[1][d1] * h[2][d2] * h[3][d3] * h[4][d4];
        g_C[idx] = h[5][d0] * h[6][d1] * h[7][d2] * h[8][d3] * h[9][d4];
    }
}

__global__ void __launch_bounds__(256) sum_kernel(const float4* __restrict__ y4) {
    extern __shared__ float smem[];
    float*  sA  = smem;                       // 7776 floats
    float4* sC4 = (float4*)(smem + TABLE);    // 7776 floats as 1944 float4 (16B aligned)

    for (int i = threadIdx.x; i < TABLE; i += blockDim.x) sA[i] = g_A[i];
    const float4* gC4 = (const float4*)g_C;
    for (int i = threadIdx.x; i < TABLE4; i += blockDim.x) sC4[i] = gC4[i];
    __syncthreads();

    float acc = 0.0f;
    int stride = gridDim.x * blockDim.x;
    #pragma unroll 4
    for (int i = blockIdx.x * blockDim.x + threadIdx.x; i < K4_TOTAL; i += stride) {
        float4 yv = __ldg(&y4[i]);
        int hi  = i / TABLE4;                 // same for 1944 consecutive float4s
        int lo4 = i - hi * TABLE4;
        float4 cv = sC4[lo4];                 // LDS.128, consecutive lanes -> conflict-free
        float  w  = sA[hi];                   // warp-uniform broadcast
        acc += w * (yv.x * cv.x + yv.y * cv.y + yv.z * cv.z + yv.w * cv.w);
    }

    // warp reduce
    #pragma unroll
    for (int off = 16; off; off >>= 1)
        acc += __shfl_xor_sync(0xffffffffu, acc, off);

    __shared__ float warp_sums[8];
    int wid = threadIdx.x >> 5;
    int lid = threadIdx.x & 31;
    if (lid == 0) warp_sums[wid] = acc;
    __syncthreads();
    if (wid == 0) {
        float v = (lid < 8) ? warp_sums[lid] : 0.0f;
        #pragma unroll
        for (int off = 4; off; off >>= 1)
            v += __shfl_xor_sync(0xffffffffu, v, off);
        if (lid == 0) atomicAdd(&g_num, v);
    }
}

__global__ void finish_kernel(float* __restrict__ out) {
    out[0] = g_num / g_den;
}

extern "C" void kernel_launch(void* const* d_in, const int* in_sizes, int n_in,
                              void* d_out, int out_size) {
    const float* X = (const float*)d_in[0];
    const float* a = (const float*)d_in[1];
    const float* b = (const float*)d_in[2];
    const float* y = (const float*)d_in[3];
    float* out = (float*)d_out;

    int smem_bytes = 2 * TABLE * (int)sizeof(float);  // 62208 B
    cudaFuncSetAttribute(sum_kernel,
                         cudaFuncAttributeMaxDynamicSharedMemorySize, smem_bytes);

    prep_kernel<<<1, 256>>>(X, a, b);
    sum_kernel<<<444, 256, smem_bytes>>>((const float4*)y);
    finish_kernel<<<1, 1>>>(out);
}

// round 5
// speedup vs baseline: 1.7605x; 1.7572x over previous
#include <cuda_runtime.h>

#define PP 6
#define NF 10
#define TABLE 7776            // 6^5
#define TABLE4 1944           // 6^5 / 4
#define K4_TOTAL 15116544     // 6^10 / 4
#define GRID 592              // 148 SMs * 4 blocks = one full wave
#define TPB 256
#define UNROLL 8

__device__ float g_partials[GRID];

// One kernel does everything except the final tiny reduction:
// builds membership values + factored weight tables in smem, then streams y.
__global__ void __launch_bounds__(TPB, 4) sum_kernel(const float* __restrict__ X,
                                                     const float* __restrict__ a,
                                                     const float* __restrict__ b,
                                                     const float4* __restrict__ y4) {
    extern __shared__ float smem[];
    float*  sC  = smem;                    // 7776 floats (features 5..9 products)
    float4* sC4 = (float4*)smem;           // same, viewed as 1944 float4
    float*  sA2 = smem + TABLE;            // 216 floats (features 0..2)
    float*  sA3 = sA2 + 216;               // 36  floats (features 3..4)
    __shared__ float h[NF][PP];
    __shared__ float warp_sums[TPB / 32];

    int tid = threadIdx.x;
    if (tid < NF * PP) {
        int i = tid / PP;
        float d  = a[tid] - X[i];
        float bb = b[tid];
        h[i][tid % PP] = expf(-(d * d) / (2.0f * bb * bb));
    }
    __syncthreads();

    // C table: low 5 base-6 digits (features 5..9), d4 least significant.
    for (int t = tid; t < TABLE; t += TPB) {
        int u = t;
        int d4 = u % PP; u /= PP;
        int d3 = u % PP; u /= PP;
        int d2 = u % PP; u /= PP;
        int d1 = u % PP; u /= PP;
        int d0 = u;
        sC[t] = h[5][d0] * h[6][d1] * h[7][d2] * h[8][d3] * h[9][d4];
    }
    // Factored A tables for the high 5 digits: A[hi] = A2[hi/36] * A3[hi%36]
    if (tid < 216) {
        int d0 = tid / 36, d1 = (tid / 6) % 6, d2 = tid % 6;
        sA2[tid] = h[0][d0] * h[1][d1] * h[2][d2];
    }
    if (tid < 36) {
        sA3[tid] = h[3][tid / 6] * h[4][tid % 6];
    }
    __syncthreads();

    const int stride = GRID * TPB;
    float acc = 0.0f;
    int i = blockIdx.x * TPB + tid;

    // Main loop: 8 independent 128B loads in flight per thread.
    while (i + (UNROLL - 1) * stride < K4_TOTAL) {
        float4 yv[UNROLL];
        #pragma unroll
        for (int j = 0; j < UNROLL; j++)
            yv[j] = __ldcs(&y4[i + j * stride]);
        #pragma unroll
        for (int j = 0; j < UNROLL; j++) {
            int idx = i + j * stride;
            int hi  = idx / TABLE4;
            int lo4 = idx - hi * TABLE4;
            int h2  = hi / 36;
            float w = sA2[h2] * sA3[hi - h2 * 36];
            float4 cv = sC4[lo4];
            acc += w * (yv[j].x * cv.x + yv[j].y * cv.y + yv[j].z * cv.z + yv[j].w * cv.w);
        }
        i += UNROLL * stride;
    }
    // Tail
    for (; i < K4_TOTAL; i += stride) {
        float4 yv = __ldcs(&y4[i]);
        int hi  = i / TABLE4;
        int lo4 = i - hi * TABLE4;
        int h2  = hi / 36;
        float w = sA2[h2] * sA3[hi - h2 * 36];
        float4 cv = sC4[lo4];
        acc += w * (yv.x * cv.x + yv.y * cv.y + yv.z * cv.z + yv.w * cv.w);
    }

    // Block reduction -> per-block partial (no atomics, no zero-init needed)
    #pragma unroll
    for (int off = 16; off; off >>= 1)
        acc += __shfl_xor_sync(0xffffffffu, acc, off);
    int wid = tid >> 5, lid = tid & 31;
    if (lid == 0) warp_sums[wid] = acc;
    __syncthreads();
    if (wid == 0) {
        float v = (lid < TPB / 32) ? warp_sums[lid] : 0.0f;
        #pragma unroll
        for (int off = 4; off; off >>= 1)
            v += __shfl_xor_sync(0xffffffffu, v, off);
        if (lid == 0) g_partials[blockIdx.x] = v;
    }
}

__global__ void finish_kernel(const float* __restrict__ X,
                              const float* __restrict__ a,
                              const float* __restrict__ b,
                              float* __restrict__ out) {
    __shared__ float ws[20];
    __shared__ float rs[NF];
    int tid = threadIdx.x;
    float v = (tid < GRID) ? g_partials[tid] : 0.0f;
    #pragma unroll
    for (int off = 16; off; off >>= 1)
        v += __shfl_xor_sync(0xffffffffu, v, off);
    int wid = tid >> 5, lid = tid & 31;
    if (lid == 0) ws[wid] = v;

    if (tid < NF) {
        float s = 0.0f;
        #pragma unroll
        for (int j = 0; j < PP; j++) {
            float d  = a[tid * PP + j] - X[tid];
            float bb = b[tid * PP + j];
            s += expf(-(d * d) / (2.0f * bb * bb));
        }
        rs[tid] = s;
    }
    __syncthreads();
    if (tid == 0) {
        float num = 0.0f;
        #pragma unroll
        for (int w = 0; w < 20; w++) num += ws[w];
        float den = 1.0f;
        #pragma unroll
        for (int i = 0; i < NF; i++) den *= rs[i];
        out[0] = num / den;
    }
}

extern "C" void kernel_launch(void* const* d_in, const int* in_sizes, int n_in,
                              void* d_out, int out_size) {
    const float* X = (const float*)d_in[0];
    const float* a = (const float*)d_in[1];
    const float* b = (const float*)d_in[2];
    const float* y = (const float*)d_in[3];
    float* out = (float*)d_out;

    int smem_bytes = (TABLE + 216 + 36) * (int)sizeof(float);  // 32112 B
    sum_kernel<<<GRID, TPB, smem_bytes>>>(X, a, b, (const float4*)y);
    finish_kernel<<<1, 640>>>(X, a, b, out);
}

// round 6
// speedup vs baseline: 1.7868x; 1.0149x over previous
#include <cuda_runtime.h>

#define PP 6
#define NF 10
#define TABLE 7776            // 6^5
#define TABLE4 1944           // 6^5 / 4
#define K4_TOTAL 15116544     // 6^10 / 4
#define GRID 592              // 148 SMs * 4 blocks = one full wave
#define TPB 256
#define UNROLL 8

__device__ float g_partials[GRID];
__device__ unsigned int g_count;   // zero-initialized; last block resets to 0 each run

// Single fused kernel: builds tables, streams y, block-reduces, and the last
// block to finish performs the final reduction + den + output write.
__global__ void __launch_bounds__(TPB, 4) sum_kernel(const float* __restrict__ X,
                                                     const float* __restrict__ a,
                                                     const float* __restrict__ b,
                                                     const float4* __restrict__ y4,
                                                     float* __restrict__ out) {
    extern __shared__ float smem[];
    float*  sC  = smem;                    // 7776 floats (features 5..9 products)
    float4* sC4 = (float4*)smem;           // same, viewed as 1944 float4
    float*  sA2 = smem + TABLE;            // 216 floats (features 0..2)
    float*  sA3 = sA2 + 216;               // 36  floats (features 3..4)
    __shared__ float h[NF][PP];
    __shared__ float warp_sums[TPB / 32];

    int tid = threadIdx.x;
    const int stride = GRID * TPB;
    const int i0 = blockIdx.x * TPB + tid;

    // Prefetch the first batch of y BEFORE the table build: these loads have no
    // smem dependency, so the ~2us table construction hides under DRAM latency.
    // First batch is always in range: max(i0) + 7*stride = 1363967 << K4_TOTAL.
    float4 yv[UNROLL];
    #pragma unroll
    for (int j = 0; j < UNROLL; j++)
        yv[j] = __ldcs(&y4[i0 + j * stride]);

    if (tid < NF * PP) {
        int i = tid / PP;
        float d  = a[tid] - X[i];
        float bb = b[tid];
        h[i][tid % PP] = expf(-(d * d) / (2.0f * bb * bb));
    }
    __syncthreads();

    // C table: low 5 base-6 digits (features 5..9), d4 least significant.
    for (int t = tid; t < TABLE; t += TPB) {
        int u = t;
        int d4 = u % PP; u /= PP;
        int d3 = u % PP; u /= PP;
        int d2 = u % PP; u /= PP;
        int d1 = u % PP; u /= PP;
        int d0 = u;
        sC[t] = h[5][d0] * h[6][d1] * h[7][d2] * h[8][d3] * h[9][d4];
    }
    // Factored A tables for the high 5 digits: A[hi] = A2[hi/36] * A3[hi%36]
    if (tid < 216) {
        int d0 = tid / 36, d1 = (tid / 6) % 6, d2 = tid % 6;
        sA2[tid] = h[0][d0] * h[1][d1] * h[2][d2];
    }
    if (tid < 36) {
        sA3[tid] = h[3][tid / 6] * h[4][tid % 6];
    }
    __syncthreads();

    float acc = 0.0f;

    // Consume prefetched batch 0.
    #pragma unroll
    for (int j = 0; j < UNROLL; j++) {
        int idx = i0 + j * stride;
        int hi  = idx / TABLE4;
        int lo4 = idx - hi * TABLE4;
        int h2  = hi / 36;
        float w = sA2[h2] * sA3[hi - h2 * 36];
        float4 cv = sC4[lo4];
        acc += w * (yv[j].x * cv.x + yv[j].y * cv.y + yv[j].z * cv.z + yv[j].w * cv.w);
    }

    // Main loop: 8 independent 128B loads in flight per thread.
    int i = i0 + UNROLL * stride;
    while (i + (UNROLL - 1) * stride < K4_TOTAL) {
        #pragma unroll
        for (int j = 0; j < UNROLL; j++)
            yv[j] = __ldcs(&y4[i + j * stride]);
        #pragma unroll
        for (int j = 0; j < UNROLL; j++) {
            int idx = i + j * stride;
            int hi  = idx / TABLE4;
            int lo4 = idx - hi * TABLE4;
            int h2  = hi / 36;
            float w = sA2[h2] * sA3[hi - h2 * 36];
            float4 cv = sC4[lo4];
            acc += w * (yv[j].x * cv.x + yv[j].y * cv.y + yv[j].z * cv.z + yv[j].w * cv.w);
        }
        i += UNROLL * stride;
    }
    // Tail
    for (; i < K4_TOTAL; i += stride) {
        float4 y1 = __ldcs(&y4[i]);
        int hi  = i / TABLE4;
        int lo4 = i - hi * TABLE4;
        int h2  = hi / 36;
        float w = sA2[h2] * sA3[hi - h2 * 36];
        float4 cv = sC4[lo4];
        acc += w * (y1.x * cv.x + y1.y * cv.y + y1.z * cv.z + y1.w * cv.w);
    }

    // Block reduction -> per-block partial
    #pragma unroll
    for (int off = 16; off; off >>= 1)
        acc += __shfl_xor_sync(0xffffffffu, acc, off);
    int wid = tid >> 5, lid = tid & 31;
    if (lid == 0) warp_sums[wid] = acc;
    __syncthreads();
    if (wid == 0 && lid == 0) {
        float v = 0.0f;
        #pragma unroll
        for (int w = 0; w < TPB / 32; w++) v += warp_sums[w];
        g_partials[blockIdx.x] = v;
    }

    // Last-block-done: final reduction + den + output, then reset counter.
    __shared__ bool is_last;
    __threadfence();
    __syncthreads();
    if (tid == 0) {
        unsigned int prev = atomicAdd(&g_count, 1u);
        is_last = (prev == GRID - 1);
    }
    __syncthreads();
    if (is_last) {
        // Reuse smem for the 592-partial reduction.
        float v = 0.0f;
        for (int t = tid; t < GRID; t += TPB) v += g_partials[t];
        #pragma unroll
        for (int off = 16; off; off >>= 1)
            v += __shfl_xor_sync(0xffffffffu, v, off);
        if (lid == 0) warp_sums[wid] = v;

        // den from membership row-sums (h[][] still valid in smem)
        __shared__ float rs[NF];
        if (tid < NF) {
            float s = 0.0f;
            #pragma unroll
            for (int j = 0; j < PP; j++) s += h[tid][j];
            rs[tid] = s;
        }
        __syncthreads();
        if (tid == 0) {
            float num = 0.0f;
            #pragma unroll
            for (int w = 0; w < TPB / 32; w++) num += warp_sums[w];
            float den = 1.0f;
            #pragma unroll
            for (int k = 0; k < NF; k++) den *= rs[k];
            out[0] = num / den;
            g_count = 0;   // reset for next graph replay (deterministic)
        }
    }
}

extern "C" void kernel_launch(void* const* d_in, const int* in_sizes, int n_in,
                              void* d_out, int out_size) {
    const float* X = (const float*)d_in[0];
    const float* a = (const float*)d_in[1];
    const float* b = (const float*)d_in[2];
    const float* y = (const float*)d_in[3];
    float* out = (float*)d_out;

    int smem_bytes = (TABLE + 216 + 36) * (int)sizeof(float);  // 32112 B
    sum_kernel<<<GRID, TPB, smem_bytes>>>(X, a, b, (const float4*)y, out);
}

// round 7
// speedup vs baseline: 1.8483x; 1.0344x over previous
#include <cuda_runtime.h>

#define PP 6
#define NF 10
#define TABLE 7776            // 6^5
#define TABLE4 1944           // 6^5 / 4 (float4 per hi-segment)
#define K4_TOTAL 15116544     // 6^10 / 4
#define GRID 592              // 148 SMs * 4 blocks = one full wave
#define TPB 256
#define UNROLL 8
#define CHUNK 25536           // ceil(K4_TOTAL / GRID)

__device__ float g_partials[GRID];
__device__ unsigned int g_count;   // zero-initialized; last block resets it each run

__global__ void __launch_bounds__(TPB, 4) sum_kernel(const float* __restrict__ X,
                                                     const float* __restrict__ a,
                                                     const float* __restrict__ b,
                                                     const float4* __restrict__ y4,
                                                     float* __restrict__ out) {
    extern __shared__ float smem[];
    float*  sC  = smem;                    // 7776 floats (features 5..9 products)
    float4* sC4 = (float4*)smem;           // same, as 1944 float4
    float*  sA2 = smem + TABLE;            // 216 floats (features 0..2)
    float*  sA3 = sA2 + 216;               // 36  floats (features 3..4)
    __shared__ float h[NF][PP];
    __shared__ float warp_sums[TPB / 32];

    const int tid   = threadIdx.x;
    const int start = blockIdx.x * CHUNK;
    const int end   = min(start + CHUNK, K4_TOTAL);

    // Prefetch first batch BEFORE table build (no smem dependency; every
    // block's chunk is >= 24768 > 2048, so batch 0 is always fully in range).
    float4 yv[UNROLL];
    const int i0 = start + tid;
    #pragma unroll
    for (int j = 0; j < UNROLL; j++)
        yv[j] = __ldcs(&y4[i0 + j * TPB]);

    if (tid < NF * PP) {
        int i = tid / PP;
        float d  = a[tid] - X[i];
        float bb = b[tid];
        h[i][tid % PP] = expf(-(d * d) / (2.0f * bb * bb));
    }
    __syncthreads();

    // C table: low 5 base-6 digits (features 5..9), f9 least significant.
    for (int t = tid; t < TABLE; t += TPB) {
        int u = t;
        int d4 = u % PP; u /= PP;
        int d3 = u % PP; u /= PP;
        int d2 = u % PP; u /= PP;
        int d1 = u % PP; u /= PP;
        int d0 = u;
        sC[t] = h[5][d0] * h[6][d1] * h[7][d2] * h[8][d3] * h[9][d4];
    }
    // Factored A tables: A[hi] = A2[hi/36] * A3[hi%36]
    if (tid < 216) {
        int d0 = tid / 36, d1 = (tid / 6) % 6, d2 = tid % 6;
        sA2[tid] = h[0][d0] * h[1][d1] * h[2][d2];
    }
    if (tid < 36) {
        sA3[tid] = h[3][tid / 6] * h[4][tid % 6];
    }
    __syncthreads();

    float acc = 0.0f;
    int i = i0;

    // Batched main loop. A thread's batch spans 7*TPB = 1792 < 1944 float4s,
    // so hi takes at most two values {hi0, hi0+1}: ONE division and four
    // scalar LDS per batch instead of two divisions + two LDS per element.
    while (i + (UNROLL - 1) * TPB < end) {
        if (i != i0) {   // batch 0 already prefetched
            #pragma unroll
            for (int j = 0; j < UNROLL; j++)
                yv[j] = __ldcs(&y4[i + j * TPB]);
        }
        unsigned int ui  = (unsigned int)i;
        unsigned int hi0 = ui / TABLE4;
        int lo0 = (int)(ui - hi0 * TABLE4);
        unsigned int hi1 = hi0 + 1; if (hi1 > TABLE - 1) hi1 = TABLE - 1;
        unsigned int q0 = hi0 / 36, q1 = hi1 / 36;
        float w0 = sA2[q0] * sA3[hi0 - q0 * 36];
        float w1 = sA2[q1] * sA3[hi1 - q1 * 36];

        #pragma unroll
        for (int j = 0; j < UNROLL; j++) {
            int lo = lo0 + j * TPB;
            bool wrap = (lo >= TABLE4);
            int  ci = wrap ? lo - TABLE4 : lo;
            float w = wrap ? w1 : w0;
            float4 cv = sC4[ci];
            float d = yv[j].x * cv.x;
            d = fmaf(yv[j].y, cv.y, d);
            d = fmaf(yv[j].z, cv.z, d);
            d = fmaf(yv[j].w, cv.w, d);
            acc = fmaf(w, d, acc);
        }
        i += UNROLL * TPB;
    }
    // Tail (few iterations per thread; full index math is fine here)
    for (; i < end; i += TPB) {
        float4 y1 = __ldcs(&y4[i]);
        unsigned int ui = (unsigned int)i;
        unsigned int hi = ui / TABLE4;
        int lo = (int)(ui - hi * TABLE4);
        unsigned int q = hi / 36;
        float w = sA2[q] * sA3[hi - q * 36];
        float4 cv = sC4[lo];
        float d = y1.x * cv.x;
        d = fmaf(y1.y, cv.y, d);
        d = fmaf(y1.z, cv.z, d);
        d = fmaf(y1.w, cv.w, d);
        acc = fmaf(w, d, acc);
    }

    // Block reduction -> per-block partial
    #pragma unroll
    for (int off = 16; off; off >>= 1)
        acc += __shfl_xor_sync(0xffffffffu, acc, off);
    int wid = tid >> 5, lid = tid & 31;
    if (lid == 0) warp_sums[wid] = acc;
    __syncthreads();
    if (tid == 0) {
        float v = 0.0f;
        #pragma unroll
        for (int w = 0; w < TPB / 32; w++) v += warp_sums[w];
        g_partials[blockIdx.x] = v;
    }

    // Last-block-done: final reduction + den + output, then reset counter.
    __shared__ bool is_last;
    __threadfence();
    __syncthreads();
    if (tid == 0) {
        unsigned int prev = atomicAdd(&g_count, 1u);
        is_last = (prev == GRID - 1);
    }
    __syncthreads();
    if (is_last) {
        float v = 0.0f;
        for (int t = tid; t < GRID; t += TPB) v += g_partials[t];
        #pragma unroll
        for (int off = 16; off; off >>= 1)
            v += __shfl_xor_sync(0xffffffffu, v, off);
        if (lid == 0) warp_sums[wid] = v;

        __shared__ float rs[NF];
        if (tid < NF) {
            float s = 0.0f;
            #pragma unroll
            for (int j = 0; j < PP; j++) s += h[tid][j];
            rs[tid] = s;
        }
        __syncthreads();
        if (tid == 0) {
            float num = 0.0f;
            #pragma unroll
            for (int w = 0; w < TPB / 32; w++) num += warp_sums[w];
            float den = 1.0f;
            #pragma unroll
            for (int k = 0; k < NF; k++) den *= rs[k];
            out[0] = num / den;
            g_count = 0;   // reset for next graph replay
        }
    }
}

extern "C" void kernel_launch(void* const* d_in, const int* in_sizes, int n_in,
                              void* d_out, int out_size) {
    const float* X = (const float*)d_in[0];
    const float* a = (const float*)d_in[1];
    const float* b = (const float*)d_in[2];
    const float* y = (const float*)d_in[3];
    float* out = (float*)d_out;

    int smem_bytes = (TABLE + 216 + 36) * (int)sizeof(float);  // 32112 B
    sum_kernel<<<GRID, TPB, smem_bytes>>>(X, a, b, (const float4*)y, out);
}

// round 8
// speedup vs baseline: 2.0309x; 1.0988x over previous
#include <cuda_runtime.h>
#include <cstdint>

#define PP 6
#define NF 10
#define SEG 1944              // float4 per hi-segment (6^5 / 4)
#define SEGB 31104            // bytes per segment stage
#define NSEG 7776             // 6^5 segments; 7776*1944 = 6^10/4 exactly
#define GRID 296              // 148 SMs * 2 blocks = one full wave
#define TPB 256
#define NSTAGE 3

__device__ float g_partials[GRID];
__device__ unsigned int g_count;   // zero-init; last block resets each run

__device__ __forceinline__ uint32_t smem_u32(const void* p) {
    uint32_t a;
    asm("{ .reg .u64 t; cvta.to.shared.u64 t, %1; cvt.u32.u64 %0, t; }"
        : "=r"(a) : "l"(p));
    return a;
}

__device__ __forceinline__ void mbar_init(uint32_t mbar, uint32_t count) {
    asm volatile("mbarrier.init.shared.b64 [%0], %1;" :: "r"(mbar), "r"(count) : "memory");
}
__device__ __forceinline__ void mbar_expect_tx(uint32_t mbar, uint32_t bytes) {
    asm volatile("mbarrier.arrive.expect_tx.shared.b64 _, [%0], %1;"
                 :: "r"(mbar), "r"(bytes) : "memory");
}
__device__ __forceinline__ void bulk_ld(uint32_t dst_smem, const void* src, uint32_t bytes,
                                        uint32_t mbar) {
    asm volatile(
        "cp.async.bulk.shared::cluster.global.mbarrier::complete_tx::bytes [%0], [%1], %2, [%3];"
        :: "r"(dst_smem), "l"(src), "r"(bytes), "r"(mbar) : "memory");
}
__device__ __forceinline__ void mbar_wait(uint32_t mbar, uint32_t parity) {
    uint32_t done;
    asm volatile(
        "{ .reg .pred p; mbarrier.try_wait.parity.acquire.cta.shared::cta.b64 p, [%1], %2;"
        " selp.b32 %0, 1, 0, p; }"
        : "=r"(done) : "r"(mbar), "r"(parity) : "memory");
    if (!done) {
        asm volatile(
            "{ .reg .pred P1; W%=:"
            " mbarrier.try_wait.parity.acquire.cta.shared::cta.b64 P1, [%0], %1, 0x989680;"
            " @P1 bra.uni D%=; bra.uni W%=; D%=: }"
            :: "r"(mbar), "r"(parity) : "memory");
    }
}

__global__ void __launch_bounds__(TPB, 2) sum_kernel(const float* __restrict__ X,
                                                     const float* __restrict__ a,
                                                     const float* __restrict__ b,
                                                     const float4* __restrict__ y4,
                                                     float* __restrict__ out) {
    extern __shared__ __align__(16) float4 ring[];   // NSTAGE * SEG float4
    __shared__ float h[NF][PP];
    __shared__ unsigned long long mbar_store[NSTAGE];
    __shared__ float warp_sums[TPB / 32];

    const int tid = threadIdx.x;
    const int blk = blockIdx.x;
    const uint32_t mb0 = smem_u32(mbar_store);

    // Segment range for this block: first 80 blocks get 27, rest 26 (sum = 7776).
    const int nseg  = 26 + (blk < 80 ? 1 : 0);
    const int base  = blk * 26 + min(blk, 80);

    // Init barriers and kick off the first NSTAGE loads immediately —
    // they overlap the h / C-register setup below.
    if (tid == 0) {
        #pragma unroll
        for (int s = 0; s < NSTAGE; s++) mbar_init(mb0 + 8u * s, 1);
    }
    __syncthreads();
    if (tid == 0) {
        #pragma unroll
        for (int k = 0; k < NSTAGE; k++) {  // nseg >= 26 > NSTAGE always
            uint32_t dst = smem_u32(&ring[k * SEG]);
            mbar_expect_tx(mb0 + 8u * k, SEGB);
            bulk_ld(dst, (const char*)y4 + (size_t)(base + k) * SEGB, SEGB, mb0 + 8u * k);
        }
    }

    // Membership values h[i][j]
    if (tid < NF * PP) {
        int i = tid / PP;
        float d  = a[tid] - X[i];
        float bb = b[tid];
        h[i][tid % PP] = expf(-(d * d) / (2.0f * bb * bb));
    }
    __syncthreads();

    // Per-thread C float4s in REGISTERS: lo positions tid + 256*j are the same
    // in every segment. lo < 1944 => j=0..6 always, j=7 only for tid < 152.
    const int nj = (tid < SEG - 7 * TPB) ? 8 : 7;   // 152
    float4 creg[8];
    #pragma unroll
    for (int j = 0; j < 8; j++) {
        if (j < nj) {
            int f0 = 4 * (tid + 256 * j);
            float c[4];
            #pragma unroll
            for (int cc = 0; cc < 4; cc++) {
                int f = f0 + cc;
                int d4 = f % 6;  f /= 6;
                int d3 = f % 6;  f /= 6;
                int d2 = f % 6;  f /= 6;
                int d1 = f % 6;  f /= 6;
                int d0 = f;
                c[cc] = h[5][d0] * h[6][d1] * h[7][d2] * h[8][d3] * h[9][d4];
            }
            creg[j] = make_float4(c[0], c[1], c[2], c[3]);
        } else {
            creg[j] = make_float4(0.f, 0.f, 0.f, 0.f);
        }
    }

    float acc = 0.0f;
    for (int k = 0; k < nseg; k++) {
        int slot = k % NSTAGE;
        uint32_t parity = (uint32_t)((k / NSTAGE) & 1);
        mbar_wait(mb0 + 8u * slot, parity);

        // Per-stage scalar weight w = A[segment] from the 5 high digits.
        int s = base + k;
        int d0 = s / 1296;  int r = s - d0 * 1296;
        int d1 = r / 216;   r -= d1 * 216;
        int d2 = r / 36;    r -= d2 * 36;
        int d3 = r / 6;
        int d4 = r - d3 * 6;
        float w = h[0][d0] * h[1][d1] * h[2][d2] * h[3][d3] * h[4][d4];

        const float4* st = &ring[slot * SEG];
        float a0 = 0.f, a1 = 0.f;
        #pragma unroll
        for (int j = 0; j < 7; j++) {
            float4 yv = st[tid + 256 * j];
            float d = yv.x * creg[j].x;
            d = fmaf(yv.y, creg[j].y, d);
            d = fmaf(yv.z, creg[j].z, d);
            d = fmaf(yv.w, creg[j].w, d);
            if (j & 1) a1 += d; else a0 += d;
        }
        if (nj == 8) {
            float4 yv = st[tid + 256 * 7];
            float d = yv.x * creg[7].x;
            d = fmaf(yv.y, creg[7].y, d);
            d = fmaf(yv.z, creg[7].z, d);
            d = fmaf(yv.w, creg[7].w, d);
            a1 += d;
        }
        acc = fmaf(w, a0 + a1, acc);

        __syncthreads();   // everyone done reading this slot
        if (tid == 0 && k + NSTAGE < nseg) {
            uint32_t dst = smem_u32(&ring[slot * SEG]);
            mbar_expect_tx(mb0 + 8u * slot, SEGB);
            bulk_ld(dst, (const char*)y4 + (size_t)(base + k + NSTAGE) * SEGB, SEGB,
                    mb0 + 8u * slot);
        }
    }

    // Block reduction -> per-block partial
    #pragma unroll
    for (int off = 16; off; off >>= 1)
        acc += __shfl_xor_sync(0xffffffffu, acc, off);
    int wid = tid >> 5, lid = tid & 31;
    if (lid == 0) warp_sums[wid] = acc;
    __syncthreads();
    if (tid == 0) {
        float v = 0.0f;
        #pragma unroll
        for (int w2 = 0; w2 < TPB / 32; w2++) v += warp_sums[w2];
        g_partials[blk] = v;
    }

    // Last-block-done: final reduction + den + output, reset counter.
    __shared__ bool is_last;
    __threadfence();
    __syncthreads();
    if (tid == 0) {
        unsigned int prev = atomicAdd(&g_count, 1u);
        is_last = (prev == GRID - 1);
    }
    __syncthreads();
    if (is_last) {
        float v = (tid < GRID) ? g_partials[tid] : 0.0f;
        if (tid + TPB < GRID) v += g_partials[tid + TPB];
        #pragma unroll
        for (int off = 16; off; off >>= 1)
            v += __shfl_xor_sync(0xffffffffu, v, off);
        if (lid == 0) warp_sums[wid] = v;

        __shared__ float rs[NF];
        if (tid < NF) {
            float s = 0.0f;
            #pragma unroll
            for (int j = 0; j < PP; j++) s += h[tid][j];
            rs[tid] = s;
        }
        __syncthreads();
        if (tid == 0) {
            float num = 0.0f;
            #pragma unroll
            for (int w2 = 0; w2 < TPB / 32; w2++) num += warp_sums[w2];
            float den = 1.0f;
            #pragma unroll
            for (int i = 0; i < NF; i++) den *= rs[i];
            out[0] = num / den;
            g_count = 0;   // deterministic graph replay
        }
    }
}

extern "C" void kernel_launch(void* const* d_in, const int* in_sizes, int n_in,
                              void* d_out, int out_size) {
    const float* X = (const float*)d_in[0];
    const float* a = (const float*)d_in[1];
    const float* b = (const float*)d_in[2];
    const float* y = (const float*)d_in[3];
    float* out = (float*)d_out;

    int smem_bytes = NSTAGE * SEGB;   // 93312 B
    cudaFuncSetAttribute(sum_kernel,
                         cudaFuncAttributeMaxDynamicSharedMemorySize, smem_bytes);
    sum_kernel<<<GRID, TPB, smem_bytes>>>(X, a, b, (const float4*)y, out);
}

// round 9
// speedup vs baseline: 2.0324x; 1.0008x over previous
#include <cuda_runtime.h>
#include <cstdint>

#define PP 6
#define NF 10
#define SEG 1944              // float4 per hi-segment (6^5 / 4)
#define SEGB 31104            // bytes per segment stage
#define GRID 288              // 288 * 27 = 7776 segments: perfectly even split
#define SEGS_PER_BLK 27
#define TPB 256
#define NSTAGE 3

__device__ float g_partials[GRID];
__device__ unsigned int g_count;   // zero-init; last block resets each run

__device__ __forceinline__ uint32_t smem_u32(const void* p) {
    uint32_t a;
    asm("{ .reg .u64 t; cvta.to.shared.u64 t, %1; cvt.u32.u64 %0, t; }"
        : "=r"(a) : "l"(p));
    return a;
}
__device__ __forceinline__ void mbar_init(uint32_t mbar, uint32_t count) {
    asm volatile("mbarrier.init.shared.b64 [%0], %1;" :: "r"(mbar), "r"(count) : "memory");
}
__device__ __forceinline__ void mbar_expect_tx(uint32_t mbar, uint32_t bytes) {
    asm volatile("mbarrier.arrive.expect_tx.shared.b64 _, [%0], %1;"
                 :: "r"(mbar), "r"(bytes) : "memory");
}
__device__ __forceinline__ void mbar_arrive(uint32_t mbar) {
    asm volatile("mbarrier.arrive.release.cta.shared::cta.b64 _, [%0];"
                 :: "r"(mbar) : "memory");
}
__device__ __forceinline__ void bulk_ld(uint32_t dst_smem, const void* src, uint32_t bytes,
                                        uint32_t mbar) {
    asm volatile(
        "cp.async.bulk.shared::cluster.global.mbarrier::complete_tx::bytes [%0], [%1], %2, [%3];"
        :: "r"(dst_smem), "l"(src), "r"(bytes), "r"(mbar) : "memory");
}
__device__ __forceinline__ void mbar_wait(uint32_t mbar, uint32_t parity) {
    uint32_t done;
    asm volatile(
        "{ .reg .pred p; mbarrier.try_wait.parity.acquire.cta.shared::cta.b64 p, [%1], %2;"
        " selp.b32 %0, 1, 0, p; }"
        : "=r"(done) : "r"(mbar), "r"(parity) : "memory");
    if (!done) {
        asm volatile(
            "{ .reg .pred P1; W%=:"
            " mbarrier.try_wait.parity.acquire.cta.shared::cta.b64 P1, [%0], %1, 0x989680;"
            " @P1 bra.uni D%=; bra.uni W%=; D%=: }"
            :: "r"(mbar), "r"(parity) : "memory");
    }
}

__global__ void __launch_bounds__(TPB, 2) sum_kernel(const float* __restrict__ X,
                                                     const float* __restrict__ a,
                                                     const float* __restrict__ b,
                                                     const float4* __restrict__ y4,
                                                     float* __restrict__ out) {
    extern __shared__ __align__(16) float4 ring[];   // NSTAGE * SEG float4
    __shared__ float h[NF][PP];
    __shared__ unsigned long long mbar_store[2 * NSTAGE];  // [full0,empty0,full1,...]
    __shared__ float warp_sums[TPB / 32];

    const int tid = threadIdx.x;
    const int blk = blockIdx.x;
    const uint32_t mb0 = smem_u32(mbar_store);
    // full[s] = mb0 + 16s, empty[s] = mb0 + 16s + 8
    const int base = blk * SEGS_PER_BLK;

    if (tid == 0) {
        #pragma unroll
        for (int s = 0; s < NSTAGE; s++) {
            mbar_init(mb0 + 16u * s, 1);            // full: tx-based
            mbar_init(mb0 + 16u * s + 8u, TPB / 32); // empty: one arrive per warp
        }
        // Kick off the first NSTAGE loads immediately; they overlap h/creg setup.
        #pragma unroll
        for (int k = 0; k < NSTAGE; k++) {
            uint32_t dst = smem_u32(&ring[k * SEG]);
            mbar_expect_tx(mb0 + 16u * k, SEGB);
            bulk_ld(dst, (const char*)y4 + (size_t)(base + k) * SEGB, SEGB, mb0 + 16u * k);
        }
    }

    // Membership values h[i][j]
    if (tid < NF * PP) {
        int i = tid / PP;
        float d  = a[tid] - X[i];
        float bb = b[tid];
        h[i][tid % PP] = expf(-(d * d) / (2.0f * bb * bb));
    }
    __syncthreads();   // h visible + mbar init visible to all

    // Per-thread C float4s in REGISTERS: lo positions tid + 256*j are identical
    // in every segment. j=0..6 always valid, j=7 only for tid < 152.
    const bool has8 = (tid < SEG - 7 * TPB);   // tid < 152
    float4 creg[8];
    #pragma unroll
    for (int j = 0; j < 8; j++) {
        if (j < 7 || has8) {
            int f0 = 4 * (tid + 256 * j);
            float c[4];
            #pragma unroll
            for (int cc = 0; cc < 4; cc++) {
                int f = f0 + cc;
                int d4 = f % 6;  f /= 6;
                int d3 = f % 6;  f /= 6;
                int d2 = f % 6;  f /= 6;
                int d1 = f % 6;  f /= 6;
                int d0 = f;
                c[cc] = h[5][d0] * h[6][d1] * h[7][d2] * h[8][d3] * h[9][d4];
            }
            creg[j] = make_float4(c[0], c[1], c[2], c[3]);
        } else {
            creg[j] = make_float4(0.f, 0.f, 0.f, 0.f);
        }
    }

    const int lid = tid & 31;
    float acc = 0.0f;

    for (int k = 0; k < SEGS_PER_BLK; k++) {
        int slot = k % NSTAGE;
        uint32_t parity = (uint32_t)((k / NSTAGE) & 1);
        uint32_t fullb  = mb0 + 16u * slot;
        uint32_t emptyb = fullb + 8u;

        mbar_wait(fullb, parity);

        // Drain stage into registers, then immediately release the slot so the
        // TMA refill overlaps with the FMA work below.
        const float4* st = &ring[slot * SEG];
        float4 yv[8];
        #pragma unroll
        for (int j = 0; j < 7; j++) yv[j] = st[tid + 256 * j];
        if (has8) yv[7] = st[tid + 256 * 7];
        __syncwarp();
        if (lid == 0) mbar_arrive(emptyb);

        // Producer: refill this slot as soon as all 8 warps have released it.
        if (tid == 0 && k + NSTAGE < SEGS_PER_BLK) {
            mbar_wait(emptyb, parity);   // round r completes with parity r&1
            mbar_expect_tx(fullb, SEGB);
            bulk_ld(smem_u32(&ring[slot * SEG]),
                    (const char*)y4 + (size_t)(base + k + NSTAGE) * SEGB, SEGB, fullb);
        }

        // Per-stage scalar weight w = A[segment] from the 5 high digits.
        int s = base + k;
        int d0 = s / 1296;  int r = s - d0 * 1296;
        int d1 = r / 216;   r -= d1 * 216;
        int d2 = r / 36;    r -= d2 * 36;
        int d3 = r / 6;
        int d4 = r - d3 * 6;
        float w = h[0][d0] * h[1][d1] * h[2][d2] * h[3][d3] * h[4][d4];

        float a0 = 0.f, a1 = 0.f;
        #pragma unroll
        for (int j = 0; j < 7; j++) {
            float d = yv[j].x * creg[j].x;
            d = fmaf(yv[j].y, creg[j].y, d);
            d = fmaf(yv[j].z, creg[j].z, d);
            d = fmaf(yv[j].w, creg[j].w, d);
            if (j & 1) a1 += d; else a0 += d;
        }
        if (has8) {
            float d = yv[7].x * creg[7].x;
            d = fmaf(yv[7].y, creg[7].y, d);
            d = fmaf(yv[7].z, creg[7].z, d);
            d = fmaf(yv[7].w, creg[7].w, d);
            a1 += d;
        }
        acc = fmaf(w, a0 + a1, acc);
    }

    // Block reduction -> per-block partial
    #pragma unroll
    for (int off = 16; off; off >>= 1)
        acc += __shfl_xor_sync(0xffffffffu, acc, off);
    int wid = tid >> 5;
    if (lid == 0) warp_sums[wid] = acc;
    __syncthreads();
    if (tid == 0) {
        float v = 0.0f;
        #pragma unroll
        for (int w2 = 0; w2 < TPB / 32; w2++) v += warp_sums[w2];
        g_partials[blk] = v;
    }

    // Last-block-done: final reduction + den + output, reset counter.
    __shared__ bool is_last;
    __threadfence();
    __syncthreads();
    if (tid == 0) {
        unsigned int prev = atomicAdd(&g_count, 1u);
        is_last = (prev == GRID - 1);
    }
    __syncthreads();
    if (is_last) {
        float v = (tid < GRID) ? g_partials[tid] : 0.0f;
        if (tid + TPB < GRID) v += g_partials[tid + TPB];
        #pragma unroll
        for (int off = 16; off; off >>= 1)
            v += __shfl_xor_sync(0xffffffffu, v, off);
        if (lid == 0) warp_sums[wid] = v;

        __shared__ float rs[NF];
        if (tid < NF) {
            float s = 0.0f;
            #pragma unroll
            for (int j = 0; j < PP; j++) s += h[tid][j];
            rs[tid] = s;
        }
        __syncthreads();
        if (tid == 0) {
            float num = 0.0f;
            #pragma unroll
            for (int w2 = 0; w2 < TPB / 32; w2++) num += warp_sums[w2];
            float den = 1.0f;
            #pragma unroll
            for (int i = 0; i < NF; i++) den *= rs[i];
            out[0] = num / den;
            g_count = 0;   // deterministic graph replay
        }
    }
}

extern "C" void kernel_launch(void* const* d_in, const int* in_sizes, int n_in,
                              void* d_out, int out_size) {
    const float* X = (const float*)d_in[0];
    const float* a = (const float*)d_in[1];
    const float* b = (const float*)d_in[2];
    const float* y = (const float*)d_in[3];
    float* out = (float*)d_out;

    int smem_bytes = NSTAGE * SEGB;   // 93312 B
    cudaFuncSetAttribute(sum_kernel,
                         cudaFuncAttributeMaxDynamicSharedMemorySize, smem_bytes);
    sum_kernel<<<GRID, TPB, smem_bytes>>>(X, a, b, (const float4*)y, out);
}